// round 6
// baseline (speedup 1.0000x reference)
#include <cuda_runtime.h>
#include <cstdint>
#include <cstddef>

#define WIDTH  2048
#define DEPTH  8
#define DP1    9
#define TMOD   242          // 30*DEPTH + 2
#define WD     16384        // WIDTH*DEPTH
#define NSPLIT 16           // i-splits for hidden
#define CHUNK  128          // WIDTH / NSPLIT

// d_out layout (float32, reference return order)
#define OFF_OUT   0ULL
#define OFF_STATE 1ULL
#define OFF_SA    18433ULL
#define OFF_SG    4478977ULL
#define OFF_OG    4495361ULL
#define OFF_GRAD  8955905ULL
#define OFF_OWG   42510337ULL

#define N_SAOG    (WIDTH * DP1 * TMOD)     // 4460544
#define NQ_SAOG   1115135                  // quads idx = 3+4q
#define NQ_GROW   4095                     // per-row quads k = 3+4q
#define GBLK      128                      // k_grad blocks (32 quads each)

// scratch (allocation-free)
__device__ float g_hpart[NSPLIT][WD];     // hidden partials (1 MB)
__device__ float g_contrib[WD];           // contrib[i*8+a], slots a=0..6
__device__ float g_m[WD];
__device__ float g_mshift[WD];            // g_mshift[t] = m[t+3]
__device__ float g_aprev[WD];
__device__ float g_out_acc;

__device__ __forceinline__ int posmod(int v, int m) {
    int r = v % m;
    return r < 0 ? r + m : r;
}

// ---------------------------------------------------------------------------
// K1: hidden partials (round-1 scheme, measured ~7.2 TB/s class)
//   hidden[k] = sum_i W[i*WD + k] * state[i, k&7]
// ---------------------------------------------------------------------------
__global__ void k_hidden_partial(const float* __restrict__ W,
                                 const float* __restrict__ state_in) {
    __shared__ float ss[CHUNK * 8];
    int k = blockIdx.x * blockDim.x + threadIdx.x;
    int i0 = blockIdx.y * CHUNK;

    if (blockIdx.x == 0 && blockIdx.y == 0 && threadIdx.x == 0) g_out_acc = 0.f;

    for (int idx = threadIdx.x; idx < CHUNK * 8; idx += blockDim.x) {
        int i = idx >> 3, d = idx & 7;
        ss[idx] = state_in[(size_t)(i0 + i) * DP1 + d];
    }
    __syncthreads();

    int d = k & 7;
    float acc = 0.f;
    const float* Wp = W + (size_t)i0 * WD + k;
#pragma unroll 8
    for (int i = 0; i < CHUNK; ++i)
        acc = fmaf(Wp[(size_t)i * WD], ss[i * 8 + d], acc);

    g_hpart[blockIdx.y][k] = acc;
}

// ---------------------------------------------------------------------------
// K2: contrib[i,a] = sum_j W[i,j,a+1] * sgrad[j,a+1],  a = 0..6
// One block per i; float4 row streaming (round-1 scheme).
// ---------------------------------------------------------------------------
__global__ void k_contrib(const float* __restrict__ W,
                          const float* __restrict__ g) {
    int i = blockIdx.x;
    const float4* Wr = reinterpret_cast<const float4*>(W + (size_t)i * WD);
    const float4* gg = reinterpret_cast<const float4*>(g);

    float acc[7] = {0, 0, 0, 0, 0, 0, 0};
    for (int j = threadIdx.x; j < WIDTH; j += blockDim.x) {
        float4 w0 = Wr[j * 2];
        float4 w1 = Wr[j * 2 + 1];
        float4 g0 = gg[j * 2];
        float4 g1 = gg[j * 2 + 1];
        acc[0] = fmaf(w0.y, g0.y, acc[0]);
        acc[1] = fmaf(w0.z, g0.z, acc[1]);
        acc[2] = fmaf(w0.w, g0.w, acc[2]);
        acc[3] = fmaf(w1.x, g1.x, acc[3]);
        acc[4] = fmaf(w1.y, g1.y, acc[4]);
        acc[5] = fmaf(w1.z, g1.z, acc[5]);
        acc[6] = fmaf(w1.w, g1.w, acc[6]);
    }
    __shared__ float red[8][7];
#pragma unroll
    for (int a = 0; a < 7; ++a)
#pragma unroll
        for (int off = 16; off; off >>= 1)
            acc[a] += __shfl_down_sync(0xffffffffu, acc[a], off);
    if ((threadIdx.x & 31) == 0) {
        int w = threadIdx.x >> 5;
#pragma unroll
        for (int a = 0; a < 7; ++a) red[w][a] = acc[a];
    }
    __syncthreads();
    if (threadIdx.x < 7) {
        float s = 0.f;
#pragma unroll
        for (int w = 0; w < 8; ++w) s += red[w][threadIdx.x];
        g_contrib[(size_t)i * 8 + threadIdx.x] = s;
    }
}

// ---------------------------------------------------------------------------
// K3: finalize — state/owg, output dot, full sg logic, m / m-shift / aprev.
// tia(a) = time + 2a - 14 (mod 242); tia==time only at a=7, (tia±1)!=time
// for all a -> all sa/og reads at a<7 hit the ORIGINAL arrays; at a=7 the
// only aliased read is this thread's own fresh state value.
// ---------------------------------------------------------------------------
__global__ void k_finalize(float* __restrict__ out,
                           const float* __restrict__ x,
                           const float* __restrict__ ow,
                           const float* __restrict__ sa_in,
                           const float* __restrict__ og_in,
                           const int* __restrict__ time_p) {
    const int k = blockIdx.x * blockDim.x + threadIdx.x;   // 0..WD-1
    const int w = k >> 3, a = k & 7;

    float h = 0.f;
#pragma unroll
    for (int c = 0; c < NSPLIT; ++c) h += g_hpart[c][k];
    float s = fmaxf(h, 0.f);

    size_t o = (size_t)w * DP1 + a + 1;
    out[OFF_STATE + o] = s;
    out[OFF_OWG + o]   = s;
    float v = ow[o] * s;
    if (a == 0) {
        float xv = x[w];
        out[OFF_STATE + (size_t)w * DP1] = xv;
        out[OFF_OWG   + (size_t)w * DP1] = xv;
        v = fmaf(ow[(size_t)w * DP1], xv, v);
    }

    const int time = *time_p;
    const int tia = posmod(time - 2 * DEPTH + 2 * (a + 1), TMOD);
    float sgv, rg, aprev;
    if (a < DEPTH - 1) {
        int t1 = (tia + 1) % TMOD;
        float rmv = sa_in[((size_t)w * DP1 + a + 2) * TMOD + t1];
        sgv = fmaf(rmv > 0.f ? 1.f : 0.f, g_contrib[k],
                   og_in[((size_t)w * DP1 + a + 1) * TMOD + tia]);
        rg = (sa_in[((size_t)w * DP1 + a + 1) * TMOD + tia] > 0.f) ? 1.f : 0.f;
        aprev = sa_in[((size_t)w * DP1 + a) * TMOD + posmod(tia - 1, TMOD)];
    } else {
        sgv = ow[(size_t)w * DP1 + DEPTH];
        rg = (s > 0.f) ? 1.f : 0.f;
        aprev = sa_in[((size_t)w * DP1 + DEPTH - 1) * TMOD + posmod(time - 1, TMOD)];
    }
    out[OFF_SG + k] = sgv;
    float mval = sgv * rg;
    g_m[k] = mval;
    if (k >= 3) g_mshift[k - 3] = mval;
    g_aprev[k] = aprev;

    __shared__ float red[8];
#pragma unroll
    for (int off = 16; off; off >>= 1)
        v += __shfl_down_sync(0xffffffffu, v, off);
    if ((threadIdx.x & 31) == 0) red[threadIdx.x >> 5] = v;
    __syncthreads();
    if (threadIdx.x == 0) {
        float t = 0.f;
#pragma unroll
        for (int i = 0; i < 8; ++i) t += red[i];
        atomicAdd(&g_out_acc, t);
    }
}

// ---------------------------------------------------------------------------
// K4: sa / og copies, SECTOR-ALIGNED stores (quad idx = 3+4q).
// ---------------------------------------------------------------------------
__global__ void k_saog(float* __restrict__ out,
                       const float* __restrict__ sa_in,
                       const float* __restrict__ og_in,
                       const float* __restrict__ ow,
                       const int* __restrict__ time_p) {
    const int time = *time_p;
    const int q = blockIdx.x * blockDim.x + threadIdx.x;
    if (q >= NQ_SAOG) return;
    const int idx = 3 + 4 * q;

    const float4* sa4 = reinterpret_cast<const float4*>(sa_in);
    const float4* og4 = reinterpret_cast<const float4*>(og_in);
    float4 sA = sa4[q], sB = sa4[q + 1];
    float4 oA = og4[q], oB = og4[q + 1];
    float sv[4] = {sA.w, sB.x, sB.y, sB.z};
    float ov[4] = {oA.w, oB.x, oB.y, oB.z};

    int t  = idx % TMOD;
    int wc = idx / TMOD;
#pragma unroll
    for (int e = 0; e < 4; ++e) {
        int tt = t + e, wcc = wc;
        if (tt >= TMOD) { tt -= TMOD; ++wcc; }
        if (tt == time) {
            sv[e] = out[OFF_STATE + wcc];
            ov[e] = ow[wcc];
        }
    }
    *reinterpret_cast<float4*>(&out[OFF_SA + idx]) = make_float4(sv[0], sv[1], sv[2], sv[3]);
    *reinterpret_cast<float4*>(&out[OFF_OG + idx]) = make_float4(ov[0], ov[1], ov[2], ov[3]);

    if (q == 0) {
#pragma unroll
        for (int e = 0; e < 3; ++e) {
            out[OFF_SA + e] = (e == time) ? out[OFF_STATE] : sa_in[e];
            out[OFF_OG + e] = (e == time) ? ow[0] : og_in[e];
        }
    }
    if (q == NQ_SAOG - 1) {
        const int it = N_SAOG - 1;
        int tt = it % TMOD, wcc = it / TMOD;
        out[OFF_SA + it] = (tt == time) ? out[OFF_STATE + wcc] : sa_in[it];
        out[OFF_OG + it] = (tt == time) ? ow[wcc] : og_in[it];
    }
}

// ---------------------------------------------------------------------------
// K5: gradients[i,j,a] = act_prev[i,a] * m[j,a], m-in-register restructure.
// 128 blocks; block owns 32 quads (lane = quad). Its m float4 is loaded ONCE
// into a register; the block loops over all 2048 rows. aprev per row = two
// broadcast loads (8 MB total L2 vs 128 MB in the old layout). Streaming
// stores (__stcs), 512B aligned per warp.
// Quad q covers k = 4q+3..4q+6; d-pattern: q even -> (3,4,5,6),
// q odd -> (7,0,1,2).
// ---------------------------------------------------------------------------
__global__ void k_grad(float* __restrict__ out) {
    const int tid  = threadIdx.x;
    const int wid  = tid >> 5, lane = tid & 31;
    const int q    = blockIdx.x * 32 + lane;
    const bool valid = (q < NQ_GROW);

    if (blockIdx.x == 0 && tid == 0) out[OFF_OUT] = g_out_acc;

    float4 mv = make_float4(0.f, 0.f, 0.f, 0.f);
    if (valid) mv = __ldg(reinterpret_cast<const float4*>(g_mshift) + q);
    const int par = q & 1;

    const bool edge = (!valid);   // the single invalid lane handles head+tail
    float m0 = 0.f, m1 = 0.f, m2 = 0.f, mt = 0.f;
    if (edge) {
        m0 = __ldg(&g_m[0]); m1 = __ldg(&g_m[1]); m2 = __ldg(&g_m[2]);
        mt = __ldg(&g_m[WD - 1]);
    }

    const float4* ap4 = reinterpret_cast<const float4*>(g_aprev);
    float* const base = out + OFF_GRAD;

#pragma unroll 4
    for (int i = wid; i < WIDTH; i += 8) {
        float4 r0 = __ldg(ap4 + i * 2);       // ap[i][0..3]
        float4 r1 = __ldg(ap4 + i * 2 + 1);   // ap[i][4..7]
        float* dst = base + (size_t)i * WD;
        if (valid) {
            float4 apv = par ? make_float4(r1.w, r0.x, r0.y, r0.z)
                             : make_float4(r0.w, r1.x, r1.y, r1.z);
            float4 v = make_float4(apv.x * mv.x, apv.y * mv.y,
                                   apv.z * mv.z, apv.w * mv.w);
            __stcs(reinterpret_cast<float4*>(dst + 3 + 4 * q), v);
        } else {
            __stcs(dst + 0, r0.x * m0);
            __stcs(dst + 1, r0.y * m1);
            __stcs(dst + 2, r0.z * m2);
            __stcs(dst + WD - 1, r1.w * mt);
        }
    }
}

// ---------------------------------------------------------------------------
extern "C" void kernel_launch(void* const* d_in, const int* in_sizes, int n_in,
                              void* d_out, int out_size) {
    const float* x    = (const float*)d_in[0];
    const float* W    = (const float*)d_in[1];
    const float* ow   = (const float*)d_in[2];
    const float* st   = (const float*)d_in[3];
    const float* sa   = (const float*)d_in[4];
    const float* sgr  = (const float*)d_in[5];
    const float* og   = (const float*)d_in[6];
    const int*   tim  = (const int*)d_in[7];
    float* out = (float*)d_out;

    k_hidden_partial<<<dim3(WD / 256, NSPLIT), 256>>>(W, st);
    k_contrib<<<WIDTH, 256>>>(W, sgr);
    k_finalize<<<WD / 256, 256>>>(out, x, ow, sa, og, tim);
    k_saog<<<(NQ_SAOG + 255) / 256, 256>>>(out, sa, og, ow, tim);
    k_grad<<<GBLK, 256>>>(out);
}

// round 7
// speedup vs baseline: 1.5139x; 1.5139x over previous
#include <cuda_runtime.h>
#include <cstdint>
#include <cstddef>

#define WIDTH  2048
#define DEPTH  8
#define DP1    9
#define TMOD   242          // 30*DEPTH + 2
#define WD     16384        // WIDTH*DEPTH
#define NSPLIT 16           // i-splits for hidden
#define CHUNK  128          // WIDTH / NSPLIT

// d_out layout (float32, reference return order)
#define OFF_OUT   0ULL
#define OFF_STATE 1ULL
#define OFF_SA    18433ULL
#define OFF_SG    4478977ULL
#define OFF_OG    4495361ULL
#define OFF_GRAD  8955905ULL
#define OFF_OWG   42510337ULL

#define N_SAOG    (WIDTH * DP1 * TMOD)     // 4460544
#define NQ_SAOG   1115135                  // quads idx = 3+4q
#define NQ_GROW   4095                     // per-row quads k = 3+4q
#define GROWS     8                        // rows per k_grad block
#define GBLK      (WIDTH / GROWS)          // 256 blocks

// scratch (allocation-free)
__device__ float g_hpart[NSPLIT][WD];     // hidden partials (1 MB)
__device__ float g_contrib[WD];           // contrib[i*8+a], slots a=1..7 used
__device__ float g_m[WD];
__device__ float g_mshift[WD];            // g_mshift[t] = m[t+3]
__device__ float g_aprev[WD];
__device__ float g_out_acc;

__device__ __forceinline__ int posmod(int v, int m) {
    int r = v % m;
    return r < 0 ? r + m : r;
}

// ---------------------------------------------------------------------------
// K1: hidden partials.  hidden[k] = sum_i W[i*WD + k] * state[i, k&7]
// ---------------------------------------------------------------------------
__global__ void k_hidden_partial(const float* __restrict__ W,
                                 const float* __restrict__ state_in) {
    __shared__ float ss[CHUNK * 8];
    int k = blockIdx.x * blockDim.x + threadIdx.x;
    int i0 = blockIdx.y * CHUNK;

    if (blockIdx.x == 0 && blockIdx.y == 0 && threadIdx.x == 0) g_out_acc = 0.f;

    for (int idx = threadIdx.x; idx < CHUNK * 8; idx += blockDim.x) {
        int i = idx >> 3, d = idx & 7;
        ss[idx] = state_in[(size_t)(i0 + i) * DP1 + d];
    }
    __syncthreads();

    int d = k & 7;
    float acc = 0.f;
    const float* Wp = W + (size_t)i0 * WD + k;
#pragma unroll 8
    for (int i = 0; i < CHUNK; ++i)
        acc = fmaf(Wp[(size_t)i * WD], ss[i * 8 + d], acc);

    g_hpart[blockIdx.y][k] = acc;
}

// ---------------------------------------------------------------------------
// K2: contrib[i,a] = sum_j W[i,j,a+1] * sgrad[j,a+1],  a = 0..6
// One block per i; float4 row streaming.
// ---------------------------------------------------------------------------
__global__ void k_contrib(const float* __restrict__ W,
                          const float* __restrict__ g) {
    int i = blockIdx.x;
    const float4* Wr = reinterpret_cast<const float4*>(W + (size_t)i * WD);
    const float4* gg = reinterpret_cast<const float4*>(g);

    float acc[7] = {0, 0, 0, 0, 0, 0, 0};
    for (int j = threadIdx.x; j < WIDTH; j += blockDim.x) {
        float4 w0 = Wr[j * 2];
        float4 w1 = Wr[j * 2 + 1];
        float4 g0 = gg[j * 2];
        float4 g1 = gg[j * 2 + 1];
        acc[0] = fmaf(w0.y, g0.y, acc[0]);
        acc[1] = fmaf(w0.z, g0.z, acc[1]);
        acc[2] = fmaf(w0.w, g0.w, acc[2]);
        acc[3] = fmaf(w1.x, g1.x, acc[3]);
        acc[4] = fmaf(w1.y, g1.y, acc[4]);
        acc[5] = fmaf(w1.z, g1.z, acc[5]);
        acc[6] = fmaf(w1.w, g1.w, acc[6]);
    }
    __shared__ float red[8][7];
#pragma unroll
    for (int a = 0; a < 7; ++a)
#pragma unroll
        for (int off = 16; off; off >>= 1)
            acc[a] += __shfl_down_sync(0xffffffffu, acc[a], off);
    if ((threadIdx.x & 31) == 0) {
        int w = threadIdx.x >> 5;
#pragma unroll
        for (int a = 0; a < 7; ++a) red[w][a] = acc[a];
    }
    __syncthreads();
    if (threadIdx.x < 7) {
        float s = 0.f;
#pragma unroll
        for (int w = 0; w < 8; ++w) s += red[w][threadIdx.x];
        g_contrib[(size_t)i * 8 + threadIdx.x] = s;
    }
}

// ---------------------------------------------------------------------------
// K3: finalize — state/owg, output dot, full sg logic, m / m-shift / aprev.
// tia(a) = time + 2a - 14 (mod 242); tia==time only at a=7, (tia±1)!=time
// for all a -> all sa/og reads at a<7 hit the ORIGINAL arrays; at a=7 the
// only aliased read is this thread's own fresh state value.
// ---------------------------------------------------------------------------
__global__ void k_finalize(float* __restrict__ out,
                           const float* __restrict__ x,
                           const float* __restrict__ ow,
                           const float* __restrict__ sa_in,
                           const float* __restrict__ og_in,
                           const int* __restrict__ time_p) {
    const int k = blockIdx.x * blockDim.x + threadIdx.x;   // 0..WD-1
    const int w = k >> 3, a = k & 7;

    float h = 0.f;
#pragma unroll
    for (int c = 0; c < NSPLIT; ++c) h += g_hpart[c][k];
    float s = fmaxf(h, 0.f);

    size_t o = (size_t)w * DP1 + a + 1;
    out[OFF_STATE + o] = s;
    out[OFF_OWG + o]   = s;
    float v = ow[o] * s;
    if (a == 0) {
        float xv = x[w];
        out[OFF_STATE + (size_t)w * DP1] = xv;
        out[OFF_OWG   + (size_t)w * DP1] = xv;
        v = fmaf(ow[(size_t)w * DP1], xv, v);
    }

    const int time = *time_p;
    const int tia = posmod(time - 2 * DEPTH + 2 * (a + 1), TMOD);
    float sgv, rg, aprev;
    if (a < DEPTH - 1) {
        int t1 = (tia + 1) % TMOD;
        float rmv = sa_in[((size_t)w * DP1 + a + 2) * TMOD + t1];
        sgv = fmaf(rmv > 0.f ? 1.f : 0.f, g_contrib[k],
                   og_in[((size_t)w * DP1 + a + 1) * TMOD + tia]);
        rg = (sa_in[((size_t)w * DP1 + a + 1) * TMOD + tia] > 0.f) ? 1.f : 0.f;
        aprev = sa_in[((size_t)w * DP1 + a) * TMOD + posmod(tia - 1, TMOD)];
    } else {
        sgv = ow[(size_t)w * DP1 + DEPTH];
        rg = (s > 0.f) ? 1.f : 0.f;
        aprev = sa_in[((size_t)w * DP1 + DEPTH - 1) * TMOD + posmod(time - 1, TMOD)];
    }
    out[OFF_SG + k] = sgv;
    float mval = sgv * rg;
    g_m[k] = mval;
    if (k >= 3) g_mshift[k - 3] = mval;
    g_aprev[k] = aprev;

    __shared__ float red[8];
#pragma unroll
    for (int off = 16; off; off >>= 1)
        v += __shfl_down_sync(0xffffffffu, v, off);
    if ((threadIdx.x & 31) == 0) red[threadIdx.x >> 5] = v;
    __syncthreads();
    if (threadIdx.x == 0) {
        float t = 0.f;
#pragma unroll
        for (int i = 0; i < 8; ++i) t += red[i];
        atomicAdd(&g_out_acc, t);
    }
}

// ---------------------------------------------------------------------------
// K4: sa / og copies, SECTOR-ALIGNED stores (quad idx = 3+4q).
// ---------------------------------------------------------------------------
__global__ void k_saog(float* __restrict__ out,
                       const float* __restrict__ sa_in,
                       const float* __restrict__ og_in,
                       const float* __restrict__ ow,
                       const int* __restrict__ time_p) {
    const int time = *time_p;
    const int q = blockIdx.x * blockDim.x + threadIdx.x;
    if (q >= NQ_SAOG) return;
    const int idx = 3 + 4 * q;

    const float4* sa4 = reinterpret_cast<const float4*>(sa_in);
    const float4* og4 = reinterpret_cast<const float4*>(og_in);
    float4 sA = sa4[q], sB = sa4[q + 1];
    float4 oA = og4[q], oB = og4[q + 1];
    float sv[4] = {sA.w, sB.x, sB.y, sB.z};
    float ov[4] = {oA.w, oB.x, oB.y, oB.z};

    int t  = idx % TMOD;
    int wc = idx / TMOD;
#pragma unroll
    for (int e = 0; e < 4; ++e) {
        int tt = t + e, wcc = wc;
        if (tt >= TMOD) { tt -= TMOD; ++wcc; }
        if (tt == time) {
            sv[e] = out[OFF_STATE + wcc];
            ov[e] = ow[wcc];
        }
    }
    *reinterpret_cast<float4*>(&out[OFF_SA + idx]) = make_float4(sv[0], sv[1], sv[2], sv[3]);
    *reinterpret_cast<float4*>(&out[OFF_OG + idx]) = make_float4(ov[0], ov[1], ov[2], ov[3]);

    if (q == 0) {
#pragma unroll
        for (int e = 0; e < 3; ++e) {
            out[OFF_SA + e] = (e == time) ? out[OFF_STATE] : sa_in[e];
            out[OFF_OG + e] = (e == time) ? ow[0] : og_in[e];
        }
    }
    if (q == NQ_SAOG - 1) {
        const int it = N_SAOG - 1;
        int tt = it % TMOD, wcc = it / TMOD;
        out[OFF_SA + it] = (tt == time) ? out[OFF_STATE + wcc] : sa_in[it];
        out[OFF_OG + it] = (tt == time) ? ow[wcc] : og_in[it];
    }
}

// ---------------------------------------------------------------------------
// K5: gradients[i,j,a] = act_prev[i,a] * m[j,a].
// 256 blocks x 8 rows each: a block's threads touch the SAME mshift quads on
// every row -> L1-resident after row 0 (L2 m-traffic 128 MB -> 16 MB), while
// each row is written as one fully contiguous 64 KB sweep (DRAM-friendly).
// Quad q covers k = 4q+3..4q+6; per-thread d-pattern fixed by tid parity.
// ---------------------------------------------------------------------------
__global__ void k_grad(float* __restrict__ out) {
    const int tid = threadIdx.x;
    if (blockIdx.x == 0 && tid == 0) out[OFF_OUT] = g_out_acc;

    const int par = tid & 1;   // q parity == tid parity (stride 256 is even)
    const float4* ms4 = reinterpret_cast<const float4*>(g_mshift);

#pragma unroll
    for (int r = 0; r < GROWS; ++r) {
        const int i = blockIdx.x * GROWS + r;
        const float* ap = g_aprev + (size_t)i * 8;
        const float4 apv = par
            ? make_float4(__ldg(ap + 7), __ldg(ap + 0), __ldg(ap + 1), __ldg(ap + 2))
            : make_float4(__ldg(ap + 3), __ldg(ap + 4), __ldg(ap + 5), __ldg(ap + 6));
        float* dst = out + OFF_GRAD + (size_t)i * WD;

#pragma unroll
        for (int s = 0; s < 16; ++s) {
            int q = tid + s * 256;
            if (q < NQ_GROW) {
                float4 mv = __ldg(ms4 + q);
                *reinterpret_cast<float4*>(dst + 3 + 4 * q) =
                    make_float4(apv.x * mv.x, apv.y * mv.y,
                                apv.z * mv.z, apv.w * mv.w);
            }
        }
        if (tid == 0) {
            dst[0] = __ldg(ap + 0) * __ldg(&g_m[0]);
            dst[1] = __ldg(ap + 1) * __ldg(&g_m[1]);
            dst[2] = __ldg(ap + 2) * __ldg(&g_m[2]);
        } else if (tid == 1) {
            dst[WD - 1] = __ldg(ap + 7) * __ldg(&g_m[WD - 1]);
        }
    }
}

// ---------------------------------------------------------------------------
extern "C" void kernel_launch(void* const* d_in, const int* in_sizes, int n_in,
                              void* d_out, int out_size) {
    const float* x    = (const float*)d_in[0];
    const float* W    = (const float*)d_in[1];
    const float* ow   = (const float*)d_in[2];
    const float* st   = (const float*)d_in[3];
    const float* sa   = (const float*)d_in[4];
    const float* sgr  = (const float*)d_in[5];
    const float* og   = (const float*)d_in[6];
    const int*   tim  = (const int*)d_in[7];
    float* out = (float*)d_out;

    k_hidden_partial<<<dim3(WD / 256, NSPLIT), 256>>>(W, st);
    k_contrib<<<WIDTH, 256>>>(W, sgr);
    k_finalize<<<WD / 256, 256>>>(out, x, ow, sa, og, tim);
    k_saog<<<(NQ_SAOG + 255) / 256, 256>>>(out, sa, og, ow, tim);
    k_grad<<<GBLK, 256>>>(out);
}

// round 8
// speedup vs baseline: 1.6664x; 1.1008x over previous
#include <cuda_runtime.h>
#include <cstdint>
#include <cstddef>

#define WIDTH  2048
#define DEPTH  8
#define DP1    9
#define TMOD   242          // 30*DEPTH + 2
#define WD     16384        // WIDTH*DEPTH
#define NSPLIT 16           // i-splits for hidden
#define CHUNK  128          // WIDTH / NSPLIT
#define HBLK   256          // hidden blocks (16 kblk x 16 split)

// d_out layout (float32, reference return order)
#define OFF_OUT   0ULL
#define OFF_STATE 1ULL
#define OFF_SA    18433ULL
#define OFF_SG    4478977ULL
#define OFF_OG    4495361ULL
#define OFF_GRAD  8955905ULL
#define OFF_OWG   42510337ULL

#define N_SAOG    (WIDTH * DP1 * TMOD)     // 4460544
#define NQ_SAOG   1115135                  // quads idx = 3+4q
#define SAOG_BLK  ((NQ_SAOG + 255) / 256)  // 4356
#define NQ_GROW   4095                     // per-row quads k = 3+4q

// scratch (allocation-free)
__device__ float g_hpart[NSPLIT][WD];     // hidden partials (1 MB)
__device__ float g_contrib[WD];
__device__ float g_m[WD];
__device__ float g_mshift[WD];            // g_mshift[t] = m[t+3]
__device__ float g_aprev[WD];
__device__ float g_out_acc;

__device__ __forceinline__ int posmod(int v, int m) {
    int r = v % m;
    return r < 0 ? r + m : r;
}

// ---------------------------------------------------------------------------
// W-phase: block-role fused. bx < HBLK -> hidden partial (float4);
// else contrib row i = bx - HBLK. Both stream W concurrently.
// ---------------------------------------------------------------------------
__global__ void k_wphase(const float* __restrict__ W,
                         const float* __restrict__ state_in,
                         const float* __restrict__ sgrad) {
    __shared__ float sh[CHUNK * 8];        // hidden: state chunk / contrib: red
    const int tid = threadIdx.x;
    const int bx  = blockIdx.x;

    if (bx == 0 && tid == 0) g_out_acc = 0.f;

    if (bx < HBLK) {
        // ---- hidden partial: hidden[k] = sum_i W[i*WD+k]*state[i,k&7] ----
        const int kblk  = bx & 15;
        const int split = bx >> 4;
        const int k4 = kblk * 1024 + tid * 4;
        const int i0 = split * CHUNK;
        const int dbase = (tid & 1) * 4;

        for (int idx = tid; idx < CHUNK * 8; idx += 256) {
            int i = idx >> 3, d = idx & 7;
            sh[idx] = state_in[(size_t)(i0 + i) * DP1 + d];
        }
        __syncthreads();

        const float* Wp = W + (size_t)i0 * WD + k4;
        float4 acc = make_float4(0.f, 0.f, 0.f, 0.f);
#pragma unroll 8
        for (int i = 0; i < CHUNK; ++i) {
            float4 w4 = *reinterpret_cast<const float4*>(Wp + (size_t)i * WD);
            float4 sv = *reinterpret_cast<const float4*>(&sh[i * 8 + dbase]);
            acc.x = fmaf(w4.x, sv.x, acc.x);
            acc.y = fmaf(w4.y, sv.y, acc.y);
            acc.z = fmaf(w4.z, sv.z, acc.z);
            acc.w = fmaf(w4.w, sv.w, acc.w);
        }
        *reinterpret_cast<float4*>(&g_hpart[split][k4]) = acc;
    } else {
        // ---- contrib[i,a] = sum_j W[i,j,a+1]*sgrad[j,a+1], a=0..6 ----
        const int i = bx - HBLK;
        const float4* Wr = reinterpret_cast<const float4*>(W + (size_t)i * WD);
        const float4* gg = reinterpret_cast<const float4*>(sgrad);

        float acc[7] = {0, 0, 0, 0, 0, 0, 0};
        for (int j = tid; j < WIDTH; j += 256) {
            float4 w0 = Wr[j * 2];
            float4 w1 = Wr[j * 2 + 1];
            float4 g0 = gg[j * 2];
            float4 g1 = gg[j * 2 + 1];
            acc[0] = fmaf(w0.y, g0.y, acc[0]);
            acc[1] = fmaf(w0.z, g0.z, acc[1]);
            acc[2] = fmaf(w0.w, g0.w, acc[2]);
            acc[3] = fmaf(w1.x, g1.x, acc[3]);
            acc[4] = fmaf(w1.y, g1.y, acc[4]);
            acc[5] = fmaf(w1.z, g1.z, acc[5]);
            acc[6] = fmaf(w1.w, g1.w, acc[6]);
        }
        float (*red)[7] = reinterpret_cast<float (*)[7]>(sh);
#pragma unroll
        for (int a = 0; a < 7; ++a)
#pragma unroll
            for (int off = 16; off; off >>= 1)
                acc[a] += __shfl_down_sync(0xffffffffu, acc[a], off);
        if ((tid & 31) == 0) {
            int w = tid >> 5;
#pragma unroll
            for (int a = 0; a < 7; ++a) red[w][a] = acc[a];
        }
        __syncthreads();
        if (tid < 7) {
            float s = 0.f;
#pragma unroll
            for (int w = 0; w < 8; ++w) s += red[w][tid];
            g_contrib[(size_t)i * 8 + tid] = s;
        }
    }
}

// ---------------------------------------------------------------------------
// finalize — state/owg, output dot, full sg logic, m / m-shift / aprev.
// tia(a) = time + 2a - 14 (mod 242); tia==time only at a=7, (tia±1)!=time
// for all a -> all sa/og reads at a<7 hit the ORIGINAL arrays; at a=7 the
// only aliased read is this thread's own fresh state value.
// ---------------------------------------------------------------------------
__global__ void k_finalize(float* __restrict__ out,
                           const float* __restrict__ x,
                           const float* __restrict__ ow,
                           const float* __restrict__ sa_in,
                           const float* __restrict__ og_in,
                           const int* __restrict__ time_p) {
    const int k = blockIdx.x * blockDim.x + threadIdx.x;   // 0..WD-1
    const int w = k >> 3, a = k & 7;

    float h = 0.f;
#pragma unroll
    for (int c = 0; c < NSPLIT; ++c) h += g_hpart[c][k];
    float s = fmaxf(h, 0.f);

    size_t o = (size_t)w * DP1 + a + 1;
    out[OFF_STATE + o] = s;
    out[OFF_OWG + o]   = s;
    float v = ow[o] * s;
    if (a == 0) {
        float xv = x[w];
        out[OFF_STATE + (size_t)w * DP1] = xv;
        out[OFF_OWG   + (size_t)w * DP1] = xv;
        v = fmaf(ow[(size_t)w * DP1], xv, v);
    }

    const int time = *time_p;
    const int tia = posmod(time - 2 * DEPTH + 2 * (a + 1), TMOD);
    float sgv, rg, aprev;
    if (a < DEPTH - 1) {
        int t1 = (tia + 1) % TMOD;
        float rmv = sa_in[((size_t)w * DP1 + a + 2) * TMOD + t1];
        sgv = fmaf(rmv > 0.f ? 1.f : 0.f, g_contrib[k],
                   og_in[((size_t)w * DP1 + a + 1) * TMOD + tia]);
        rg = (sa_in[((size_t)w * DP1 + a + 1) * TMOD + tia] > 0.f) ? 1.f : 0.f;
        aprev = sa_in[((size_t)w * DP1 + a) * TMOD + posmod(tia - 1, TMOD)];
    } else {
        sgv = ow[(size_t)w * DP1 + DEPTH];
        rg = (s > 0.f) ? 1.f : 0.f;
        aprev = sa_in[((size_t)w * DP1 + DEPTH - 1) * TMOD + posmod(time - 1, TMOD)];
    }
    out[OFF_SG + k] = sgv;
    float mval = sgv * rg;
    g_m[k] = mval;
    if (k >= 3) g_mshift[k - 3] = mval;
    g_aprev[k] = aprev;

    __shared__ float red[8];
#pragma unroll
    for (int off = 16; off; off >>= 1)
        v += __shfl_down_sync(0xffffffffu, v, off);
    if ((threadIdx.x & 31) == 0) red[threadIdx.x >> 5] = v;
    __syncthreads();
    if (threadIdx.x == 0) {
        float t = 0.f;
#pragma unroll
        for (int i = 0; i < 8; ++i) t += red[i];
        atomicAdd(&g_out_acc, t);
    }
}

// ---------------------------------------------------------------------------
// Post-phase: block-role fused. bx < SAOG_BLK -> saog copy quad block;
// else grad row i = bx - SAOG_BLK (round-5 scheme: block-per-row, mshift).
// ---------------------------------------------------------------------------
__global__ void k_post(float* __restrict__ out,
                       const float* __restrict__ sa_in,
                       const float* __restrict__ og_in,
                       const float* __restrict__ ow,
                       const int* __restrict__ time_p) {
    const int tid = threadIdx.x;
    const int bx  = blockIdx.x;

    if (bx < SAOG_BLK) {
        // ---- saog: sector-aligned copies (quad idx = 3+4q) ----
        const int time = *time_p;
        const int q = bx * 256 + tid;
        if (q >= NQ_SAOG) return;
        const int idx = 3 + 4 * q;

        const float4* sa4 = reinterpret_cast<const float4*>(sa_in);
        const float4* og4 = reinterpret_cast<const float4*>(og_in);
        float4 sA = sa4[q], sB = sa4[q + 1];
        float4 oA = og4[q], oB = og4[q + 1];
        float sv[4] = {sA.w, sB.x, sB.y, sB.z};
        float ov[4] = {oA.w, oB.x, oB.y, oB.z};

        int t  = idx % TMOD;
        int wc = idx / TMOD;
#pragma unroll
        for (int e = 0; e < 4; ++e) {
            int tt = t + e, wcc = wc;
            if (tt >= TMOD) { tt -= TMOD; ++wcc; }
            if (tt == time) {
                sv[e] = out[OFF_STATE + wcc];
                ov[e] = ow[wcc];
            }
        }
        *reinterpret_cast<float4*>(&out[OFF_SA + idx]) =
            make_float4(sv[0], sv[1], sv[2], sv[3]);
        *reinterpret_cast<float4*>(&out[OFF_OG + idx]) =
            make_float4(ov[0], ov[1], ov[2], ov[3]);

        if (q == 0) {
#pragma unroll
            for (int e = 0; e < 3; ++e) {
                out[OFF_SA + e] = (e == time) ? out[OFF_STATE] : sa_in[e];
                out[OFF_OG + e] = (e == time) ? ow[0] : og_in[e];
            }
        }
        if (q == NQ_SAOG - 1) {
            const int it = N_SAOG - 1;
            int tt = it % TMOD, wcc = it / TMOD;
            out[OFF_SA + it] = (tt == time) ? out[OFF_STATE + wcc] : sa_in[it];
            out[OFF_OG + it] = (tt == time) ? ow[wcc] : og_in[it];
        }
    } else {
        // ---- grad row: gradients[i,j,a] = aprev[i,a] * m[j,a] ----
        const int i = bx - SAOG_BLK;
        if (i == 0 && tid == 0) out[OFF_OUT] = g_out_acc;

        const float* ap = g_aprev + (size_t)i * 8;
        const float4 apv = (tid & 1)
            ? make_float4(__ldg(ap + 7), __ldg(ap + 0), __ldg(ap + 1), __ldg(ap + 2))
            : make_float4(__ldg(ap + 3), __ldg(ap + 4), __ldg(ap + 5), __ldg(ap + 6));

        float* dst = out + OFF_GRAD + (size_t)i * WD;
        const float4* ms4 = reinterpret_cast<const float4*>(g_mshift);

        for (int q = tid; q < NQ_GROW; q += 256) {
            float4 mv = ms4[q];
            *reinterpret_cast<float4*>(dst + 3 + 4 * q) =
                make_float4(apv.x * mv.x, apv.y * mv.y,
                            apv.z * mv.z, apv.w * mv.w);
        }
        if (tid == 0) {
            dst[0] = __ldg(ap + 0) * g_m[0];
            dst[1] = __ldg(ap + 1) * g_m[1];
            dst[2] = __ldg(ap + 2) * g_m[2];
        } else if (tid == 1) {
            dst[WD - 1] = __ldg(ap + 7) * g_m[WD - 1];
        }
    }
}

// ---------------------------------------------------------------------------
extern "C" void kernel_launch(void* const* d_in, const int* in_sizes, int n_in,
                              void* d_out, int out_size) {
    const float* x    = (const float*)d_in[0];
    const float* W    = (const float*)d_in[1];
    const float* ow   = (const float*)d_in[2];
    const float* st   = (const float*)d_in[3];
    const float* sa   = (const float*)d_in[4];
    const float* sgr  = (const float*)d_in[5];
    const float* og   = (const float*)d_in[6];
    const int*   tim  = (const int*)d_in[7];
    float* out = (float*)d_out;

    k_wphase<<<HBLK + WIDTH, 256>>>(W, st, sgr);
    k_finalize<<<WD / 256, 256>>>(out, x, ow, sa, og, tim);
    k_post<<<SAOG_BLK + WIDTH, 256>>>(out, sa, og, ow, tim);
}